// round 11
// baseline (speedup 1.0000x reference)
#include <cuda_runtime.h>
#include <cuda_fp16.h>
#include <cstdint>

#define D_MODEL 1024
#define D_FF    4096
#define NEXP    8
#define NTOK    4096
#define MAXTILES 40
#define NROWPAD (MAXTILES * 128)   // 5120 padded rows
#define KSPLIT  2                  // split-K factor for GEMM2

// ---------------------------------------------------------------------------
// Device-global scratch (allocation-free, graph-capture safe)
// ---------------------------------------------------------------------------
__device__ int   g_tok[NEXP * NTOK];
__device__ int   g_cnt[NEXP];
__device__ float g_gate[NTOK];
__device__ int   g_poff[NEXP];
__device__ int   g_tile_expert[MAXTILES];
__device__ int   g_row2tok[NROWPAD];

__device__ __align__(16) __half g_xh[(size_t)NROWPAD * D_MODEL];
__device__ __align__(16) __half g_W1h[(size_t)NEXP * D_FF * D_MODEL];  // [E][N][K]
__device__ __align__(16) __half g_W2h[(size_t)NEXP * D_MODEL * D_FF];  // [E][N][K]
__device__ __align__(16) __half g_Hh[(size_t)NROWPAD * D_FF];
__device__ __align__(16) float  g_part[(size_t)KSPLIT * NROWPAD * D_MODEL];

// ---------------------------------------------------------------------------
// helpers
// ---------------------------------------------------------------------------
__device__ __forceinline__ uint32_t smem_u32(const void* p) {
    uint32_t a;
    asm("{ .reg .u64 t; cvta.to.shared.u64 t, %1; cvt.u32.u64 %0, t; }"
        : "=r"(a) : "l"(p));
    return a;
}
// swizzled byte offset into a [rows][32 halfs] (64B/row) smem tile
__device__ __forceinline__ uint32_t sw_off(int r, int kelem) {
    const int chunk = kelem >> 3;                       // 16B chunk within row
    return (uint32_t)(r * 64 + (((chunk ^ ((r >> 1) & 3)) & 3) << 4)
                      + ((kelem & 7) << 1));
}
__device__ __forceinline__ void ldsm4(uint32_t* r, uint32_t addr) {
    asm volatile("ldmatrix.sync.aligned.m8n8.x4.shared.b16 {%0,%1,%2,%3}, [%4];"
                 : "=r"(r[0]), "=r"(r[1]), "=r"(r[2]), "=r"(r[3]) : "r"(addr));
}
__device__ __forceinline__ void mma16816(float* d, const uint32_t* a,
                                         const uint32_t* b) {
    asm volatile("mma.sync.aligned.m16n8k16.row.col.f32.f16.f16.f32 "
                 "{%0,%1,%2,%3}, {%4,%5,%6,%7}, {%8,%9}, {%0,%1,%2,%3};"
                 : "+f"(d[0]), "+f"(d[1]), "+f"(d[2]), "+f"(d[3])
                 : "r"(a[0]), "r"(a[1]), "r"(a[2]), "r"(a[3]),
                   "r"(b[0]), "r"(b[1]));
}
#define CP_ASYNC16(dst, src) \
    asm volatile("cp.async.cg.shared.global [%0], [%1], 16;" :: "r"(dst), "l"(src))
#define CP_COMMIT()  asm volatile("cp.async.commit_group;" ::: "memory")
#define CP_WAIT1()   asm volatile("cp.async.wait_group 1;" ::: "memory")

// ---------------------------------------------------------------------------
// init / router / build  (unchanged, verified)
// ---------------------------------------------------------------------------
__global__ void init_kernel() {
    if (threadIdx.x < NEXP) g_cnt[threadIdx.x] = 0;
}

__global__ void router_kernel(const float* __restrict__ x,
                              const float* __restrict__ rW,
                              const float* __restrict__ rb) {
    __shared__ float xs[D_MODEL];
    __shared__ float logits[NEXP];
    const int token = blockIdx.x;
    ((float4*)xs)[threadIdx.x] = ((const float4*)(x + (size_t)token * D_MODEL))[threadIdx.x];
    __syncthreads();
    const int e = threadIdx.x >> 5, lane = threadIdx.x & 31;
    float s = 0.f;
    #pragma unroll 8
    for (int d = lane; d < D_MODEL; d += 32) s += xs[d] * rW[d * NEXP + e];
    #pragma unroll
    for (int o = 16; o > 0; o >>= 1) s += __shfl_down_sync(0xffffffffu, s, o);
    if (lane == 0) logits[e] = s + rb[e];
    __syncthreads();
    if (threadIdx.x == 0) {
        float mx = logits[0]; int am = 0;
        #pragma unroll
        for (int i = 1; i < NEXP; i++)
            if (logits[i] > mx) { mx = logits[i]; am = i; }
        float sum = 0.f;
        #pragma unroll
        for (int i = 0; i < NEXP; i++) sum += expf(logits[i] - mx);
        const int pos = atomicAdd(&g_cnt[am], 1);
        g_tok[am * NTOK + pos] = token;
        g_gate[token] = 1.0f / sum;
    }
}

__global__ void build_kernel() {
    if (threadIdx.x != 0) return;
    int off = 0;
    for (int e = 0; e < NEXP; e++) {
        g_poff[e] = off;
        int tiles = (g_cnt[e] + 127) >> 7;
        for (int t = 0; t < tiles; t++) g_tile_expert[(off >> 7) + t] = e;
        off += tiles << 7;
    }
    for (int t = off >> 7; t < MAXTILES; t++) g_tile_expert[t] = -1;
}

// ---------------------------------------------------------------------------
// convert_x: gather token rows into packed/padded order, fp16
// ---------------------------------------------------------------------------
__global__ void convert_x_kernel(const float* __restrict__ x) {
    const int row = blockIdx.x;
    const int e = g_tile_expert[row >> 7];
    int tok = -1;
    if (e >= 0) {
        const int local = row - g_poff[e];
        if (local < g_cnt[e]) tok = g_tok[e * NTOK + local];
    }
    if (threadIdx.x == 0) g_row2tok[row] = tok;
    const int d0 = threadIdx.x * 4;
    float4 v = make_float4(0.f, 0.f, 0.f, 0.f);
    if (tok >= 0) v = *(const float4*)(x + (size_t)tok * D_MODEL + d0);
    union { __half b[4]; uint2 u; } H;
    H.b[0] = __float2half(v.x); H.b[1] = __float2half(v.y);
    H.b[2] = __float2half(v.z); H.b[3] = __float2half(v.w);
    *(uint2*)(g_xh + (size_t)row * D_MODEL + d0) = H.u;
}

// ---------------------------------------------------------------------------
// transpose_w: [E][K][N] fp32 -> [E][N][K] fp16  (round-6 verified)
// ---------------------------------------------------------------------------
template<int WHICH>  // 1 -> W1, 2 -> W2
__global__ __launch_bounds__(256)
void transpose_w_kernel(const float* __restrict__ W, int K, int N) {
    __shared__ float t[64][65];
    const int e = blockIdx.z, k0 = blockIdx.x * 64, n0 = blockIdx.y * 64;
    const int tid = threadIdx.x;
    __half* __restrict__ Wh = (WHICH == 1) ? g_W1h : g_W2h;

    const int c4 = tid & 15, r0 = tid >> 4;
    #pragma unroll
    for (int i = 0; i < 4; i++) {
        const int kr = r0 + i * 16;
        const float4 v = *(const float4*)(W + ((size_t)e * K + k0 + kr) * N + n0 + c4 * 4);
        t[kr][c4 * 4 + 0] = v.x; t[kr][c4 * 4 + 1] = v.y;
        t[kr][c4 * 4 + 2] = v.z; t[kr][c4 * 4 + 3] = v.w;
    }
    __syncthreads();
    #pragma unroll
    for (int i = 0; i < 2; i++) {
        const int u = tid + 256 * i;
        const int n = u >> 3, ch = u & 7;
        union { __half h[8]; uint4 q; } P;
        #pragma unroll
        for (int j = 0; j < 8; j++) P.h[j] = __float2half(t[ch * 8 + j][n]);
        *(uint4*)(Wh + ((size_t)e * N + n0 + n) * K + k0 + ch * 8) = P.q;
    }
}

// ---------------------------------------------------------------------------
// fp16 mma grouped GEMM: 128x128 tile, BK=32, 3-stage cp.async ring,
// 2 CTAs/SM. Warps: 4(m) x 2(n), warp tile 32m x 64n. acc = 64 floats.
// stage: A 8K | B 8K = 16K; 3 stages = 48K   (round-9 verified)
// PARTIAL: write fp32 partials to g_part[blockIdx.z] (split-K GEMM2)
// ---------------------------------------------------------------------------
#define STAGE_BYTES 16384
#define SMEM_GEMM   (3 * STAGE_BYTES)

template<int R>
__device__ __forceinline__ void stage_cp(const __half* __restrict__ src,
                                         int ld, uint32_t dst, int tid) {
    #pragma unroll
    for (int u = tid; u < R * 4; u += 256) {
        const int r = u >> 2, c = u & 3;
        const uint32_t d = dst + r * 64 + (((c ^ ((r >> 1) & 3)) & 3) << 4);
        CP_ASYNC16(d, src + (size_t)r * ld + c * 8);
    }
}

template<int KTOT, int KCHUNK, int NTOT, bool IS_G1, bool PARTIAL>
__global__ __launch_bounds__(256, 2)
void moe_gemm_mma(const float* __restrict__ bias, float* __restrict__ outp) {
    const int e = g_tile_expert[blockIdx.y];
    if (e < 0) return;
    const int m0 = blockIdx.y * 128;
    const int n0 = blockIdx.x * 128;
    const int kz = PARTIAL ? blockIdx.z * KCHUNK : 0;

    extern __shared__ char smem[];
    const uint32_t sb = smem_u32(smem);
    const int tid = threadIdx.x, lane = tid & 31, wid = tid >> 5;
    const int wm = (wid & 3) * 32;        // warp m-base (4 warps in m)
    const int wn = (wid >> 2) * 64;       // warp n-base (2 warps in n)

    const __half* Ah = (IS_G1 ? g_xh : g_Hh) + (size_t)m0 * KTOT + kz;
    const __half* Bw = (IS_G1 ? g_W1h : g_W2h) + ((size_t)e * NTOT + n0) * KTOT + kz;

    // ldmatrix lane addressing (verified)
    const int a_r = wm + (lane & 15);                       // + mt*16
    const int a_k = (lane >> 4) * 8;                        // + ks*16
    const int b_r = wn + (lane & 7) + ((lane >> 4) << 3);   // + nt*16
    const int b_k = ((lane >> 3) & 1) * 8;                  // + ks*16

    float acc[64];
    #pragma unroll
    for (int i = 0; i < 64; i++) acc[i] = 0.f;

    const int NSTAGE = KCHUNK / 32;

    auto issue = [&](int s, int buf) {
        const uint32_t base = sb + buf * STAGE_BYTES;
        const int k0 = s * 32;
        stage_cp<128>(Ah + k0, KTOT, base,        tid);
        stage_cp<128>(Bw + k0, KTOT, base + 8192, tid);
    };

    issue(0, 0); CP_COMMIT();
    issue(1, 1); CP_COMMIT();

    int buf = 0;
    #pragma unroll 1
    for (int s = 0; s < NSTAGE; s++) {
        CP_WAIT1();
        __syncthreads();
        const int nbuf = (buf + 2 >= 3) ? buf - 1 : buf + 2;
        if (s + 2 < NSTAGE) issue(s + 2, nbuf);
        CP_COMMIT();

        const uint32_t As = sb + buf * STAGE_BYTES;
        const uint32_t Bs = As + 8192;
        #pragma unroll
        for (int ks = 0; ks < 2; ks++) {
            uint32_t a[2][4];
            #pragma unroll
            for (int mt = 0; mt < 2; mt++)
                ldsm4(a[mt], As + sw_off(a_r + mt * 16, ks * 16 + a_k));
            #pragma unroll
            for (int nt = 0; nt < 4; nt++) {
                uint32_t b[4];
                ldsm4(b, Bs + sw_off(b_r + nt * 16, ks * 16 + b_k));
                #pragma unroll
                for (int mt = 0; mt < 2; mt++) {
                    float* d0 = acc + (mt * 8 + 2 * nt) * 4;
                    float* d1 = acc + (mt * 8 + 2 * nt + 1) * 4;
                    mma16816(d0, a[mt], b);
                    mma16816(d1, a[mt], b + 2);
                }
            }
        }
        buf = (buf + 1 == 3) ? 0 : buf + 1;
    }

    // ---- epilogue (verified mapping) ----
    const int gq = lane >> 2, tq = lane & 3;
    float* const pbase = PARTIAL
        ? g_part + (size_t)blockIdx.z * NROWPAD * D_MODEL : nullptr;
    #pragma unroll
    for (int mt = 0; mt < 2; mt++) {
        #pragma unroll
        for (int half = 0; half < 2; half++) {   // row, row+8
            const int row = m0 + wm + mt * 16 + gq + half * 8;
            #pragma unroll
            for (int nt = 0; nt < 8; nt++) {
                const int col = n0 + wn + nt * 8 + tq * 2;
                const float* d = acc + (mt * 8 + nt) * 4 + half * 2;
                if (IS_G1) {
                    float v0 = d[0] + bias[e * D_FF + col];
                    float v1 = d[1] + bias[e * D_FF + col + 1];
                    v0 = fmaxf(v0, 0.f); v1 = fmaxf(v1, 0.f);
                    __half2 H;
                    H.x = __float2half(v0); H.y = __float2half(v1);
                    *(__half2*)(g_Hh + (size_t)row * D_FF + col) = H;
                } else {
                    float2 o; o.x = d[0]; o.y = d[1];
                    *(float2*)(pbase + (size_t)row * D_MODEL + col) = o;
                }
            }
        }
    }
}

// ---------------------------------------------------------------------------
// reduce: out[tok] = gate * (sum_z part[z][row] + b2)   (deterministic)
// ---------------------------------------------------------------------------
__global__ void reduce_kernel(const float* __restrict__ b2,
                              float* __restrict__ outp) {
    const int row = blockIdx.x;
    const int tok = g_row2tok[row];
    if (tok < 0) return;
    const float gate = g_gate[tok];
    const int c0 = threadIdx.x * 4;
    float4 s = *(const float4*)(g_part + (size_t)row * D_MODEL + c0);
    #pragma unroll
    for (int z = 1; z < KSPLIT; z++) {
        const float4 p = *(const float4*)(g_part + (size_t)z * NROWPAD * D_MODEL
                                          + (size_t)row * D_MODEL + c0);
        s.x += p.x; s.y += p.y; s.z += p.z; s.w += p.w;
    }
    const int e = g_tile_expert[row >> 7];
    const float4 b = *(const float4*)(b2 + e * D_MODEL + c0);
    float4 o;
    o.x = (s.x + b.x) * gate; o.y = (s.y + b.y) * gate;
    o.z = (s.z + b.z) * gate; o.w = (s.w + b.w) * gate;
    *(float4*)(outp + (size_t)tok * D_MODEL + c0) = o;
}

// ---------------------------------------------------------------------------
// kernel_launch
// ---------------------------------------------------------------------------
extern "C" void kernel_launch(void* const* d_in, const int* in_sizes, int n_in,
                              void* d_out, int out_size) {
    const float* x  = (const float*)d_in[0];
    const float* rW = (const float*)d_in[1];
    const float* rb = (const float*)d_in[2];
    const float* W1 = (const float*)d_in[3];
    const float* b1 = (const float*)d_in[4];
    const float* W2 = (const float*)d_in[5];
    const float* b2 = (const float*)d_in[6];
    float* out = (float*)d_out;

    cudaFuncSetAttribute(
        moe_gemm_mma<D_MODEL, D_MODEL, D_FF, true, false>,
        cudaFuncAttributeMaxDynamicSharedMemorySize, SMEM_GEMM);
    cudaFuncSetAttribute(
        moe_gemm_mma<D_FF, D_FF / KSPLIT, D_MODEL, false, true>,
        cudaFuncAttributeMaxDynamicSharedMemorySize, SMEM_GEMM);

    init_kernel<<<1, 32>>>();
    router_kernel<<<NTOK, 256>>>(x, rW, rb);
    build_kernel<<<1, 32>>>();
    convert_x_kernel<<<NROWPAD, 256>>>(x);
    {   // W1: K=1024, N=4096 -> [E][4096][1024]
        dim3 grid(D_MODEL / 64, D_FF / 64, NEXP);
        transpose_w_kernel<1><<<grid, 256>>>(W1, D_MODEL, D_FF);
    }
    {   // W2: K=4096, N=1024 -> [E][1024][4096]
        dim3 grid(D_FF / 64, D_MODEL / 64, NEXP);
        transpose_w_kernel<2><<<grid, 256>>>(W2, D_FF, D_MODEL);
    }
    {   // GEMM1: H = relu(Xp @ W1t^T + b1), K=1024, N=4096
        dim3 grid(D_FF / 128, MAXTILES, 1);
        moe_gemm_mma<D_MODEL, D_MODEL, D_FF, true, false>
            <<<grid, 256, SMEM_GEMM>>>(b1, nullptr);
    }
    {   // GEMM2 split-K=2: partials = H @ W2t^T, K-chunk 2048
        dim3 grid(D_MODEL / 128, MAXTILES, KSPLIT);
        moe_gemm_mma<D_FF, D_FF / KSPLIT, D_MODEL, false, true>
            <<<grid, 256, SMEM_GEMM>>>(nullptr, nullptr);
    }
    reduce_kernel<<<NROWPAD, 256>>>(b2, out);
}

// round 12
// speedup vs baseline: 1.0307x; 1.0307x over previous
#include <cuda_runtime.h>
#include <cuda_fp16.h>
#include <cstdint>

#define D_MODEL 1024
#define D_FF    4096
#define NEXP    8
#define NTOK    4096
#define MAXTILES 40
#define NROWPAD (MAXTILES * 128)   // 5120 padded rows

// ---------------------------------------------------------------------------
// Device-global scratch (allocation-free, graph-capture safe)
// ---------------------------------------------------------------------------
__device__ int   g_tok[NEXP * NTOK];
__device__ int   g_cnt[NEXP];
__device__ float g_gate[NTOK];
__device__ int   g_poff[NEXP];
__device__ int   g_tile_expert[MAXTILES];
__device__ int   g_row2tok[NROWPAD];

__device__ __align__(16) __half g_xh[(size_t)NROWPAD * D_MODEL];
__device__ __align__(16) __half g_W1h[(size_t)NEXP * D_FF * D_MODEL];  // [E][N][K]
__device__ __align__(16) __half g_W2h[(size_t)NEXP * D_MODEL * D_FF];  // [E][N][K]
__device__ __align__(16) __half g_Hh[(size_t)NROWPAD * D_FF];

// ---------------------------------------------------------------------------
// side stream + fork/join events, created before the harness's memory
// checkpoints (static init). Work per kernel_launch call is identical and
// deterministic; these are reused every call.
// ---------------------------------------------------------------------------
static cudaStream_t g_sB;
static cudaEvent_t  g_ev0, g_evT1, g_evT2;
static struct StreamInit {
    StreamInit() {
        cudaStreamCreateWithFlags(&g_sB, cudaStreamNonBlocking);
        cudaEventCreateWithFlags(&g_ev0,  cudaEventDisableTiming);
        cudaEventCreateWithFlags(&g_evT1, cudaEventDisableTiming);
        cudaEventCreateWithFlags(&g_evT2, cudaEventDisableTiming);
    }
} g_stream_init;

// ---------------------------------------------------------------------------
// helpers
// ---------------------------------------------------------------------------
__device__ __forceinline__ uint32_t smem_u32(const void* p) {
    uint32_t a;
    asm("{ .reg .u64 t; cvta.to.shared.u64 t, %1; cvt.u32.u64 %0, t; }"
        : "=r"(a) : "l"(p));
    return a;
}
// swizzled byte offset into a [rows][32 halfs] (64B/row) smem tile
__device__ __forceinline__ uint32_t sw_off(int r, int kelem) {
    const int chunk = kelem >> 3;                       // 16B chunk within row
    return (uint32_t)(r * 64 + (((chunk ^ ((r >> 1) & 3)) & 3) << 4)
                      + ((kelem & 7) << 1));
}
__device__ __forceinline__ void ldsm4(uint32_t* r, uint32_t addr) {
    asm volatile("ldmatrix.sync.aligned.m8n8.x4.shared.b16 {%0,%1,%2,%3}, [%4];"
                 : "=r"(r[0]), "=r"(r[1]), "=r"(r[2]), "=r"(r[3]) : "r"(addr));
}
__device__ __forceinline__ void mma16816(float* d, const uint32_t* a,
                                         const uint32_t* b) {
    asm volatile("mma.sync.aligned.m16n8k16.row.col.f32.f16.f16.f32 "
                 "{%0,%1,%2,%3}, {%4,%5,%6,%7}, {%8,%9}, {%0,%1,%2,%3};"
                 : "+f"(d[0]), "+f"(d[1]), "+f"(d[2]), "+f"(d[3])
                 : "r"(a[0]), "r"(a[1]), "r"(a[2]), "r"(a[3]),
                   "r"(b[0]), "r"(b[1]));
}
#define CP_ASYNC16(dst, src) \
    asm volatile("cp.async.cg.shared.global [%0], [%1], 16;" :: "r"(dst), "l"(src))
#define CP_COMMIT()  asm volatile("cp.async.commit_group;" ::: "memory")
#define CP_WAIT1()   asm volatile("cp.async.wait_group 1;" ::: "memory")

// ---------------------------------------------------------------------------
// init / router / build  (unchanged, verified)
// ---------------------------------------------------------------------------
__global__ void init_kernel() {
    if (threadIdx.x < NEXP) g_cnt[threadIdx.x] = 0;
}

__global__ void router_kernel(const float* __restrict__ x,
                              const float* __restrict__ rW,
                              const float* __restrict__ rb) {
    __shared__ float xs[D_MODEL];
    __shared__ float logits[NEXP];
    const int token = blockIdx.x;
    ((float4*)xs)[threadIdx.x] = ((const float4*)(x + (size_t)token * D_MODEL))[threadIdx.x];
    __syncthreads();
    const int e = threadIdx.x >> 5, lane = threadIdx.x & 31;
    float s = 0.f;
    #pragma unroll 8
    for (int d = lane; d < D_MODEL; d += 32) s += xs[d] * rW[d * NEXP + e];
    #pragma unroll
    for (int o = 16; o > 0; o >>= 1) s += __shfl_down_sync(0xffffffffu, s, o);
    if (lane == 0) logits[e] = s + rb[e];
    __syncthreads();
    if (threadIdx.x == 0) {
        float mx = logits[0]; int am = 0;
        #pragma unroll
        for (int i = 1; i < NEXP; i++)
            if (logits[i] > mx) { mx = logits[i]; am = i; }
        float sum = 0.f;
        #pragma unroll
        for (int i = 0; i < NEXP; i++) sum += expf(logits[i] - mx);
        const int pos = atomicAdd(&g_cnt[am], 1);
        g_tok[am * NTOK + pos] = token;
        g_gate[token] = 1.0f / sum;
    }
}

__global__ void build_kernel() {
    if (threadIdx.x != 0) return;
    int off = 0;
    for (int e = 0; e < NEXP; e++) {
        g_poff[e] = off;
        int tiles = (g_cnt[e] + 127) >> 7;
        for (int t = 0; t < tiles; t++) g_tile_expert[(off >> 7) + t] = e;
        off += tiles << 7;
    }
    for (int t = off >> 7; t < MAXTILES; t++) g_tile_expert[t] = -1;
}

// ---------------------------------------------------------------------------
// convert_x: gather token rows into packed/padded order, fp16
// ---------------------------------------------------------------------------
__global__ void convert_x_kernel(const float* __restrict__ x) {
    const int row = blockIdx.x;
    const int e = g_tile_expert[row >> 7];
    int tok = -1;
    if (e >= 0) {
        const int local = row - g_poff[e];
        if (local < g_cnt[e]) tok = g_tok[e * NTOK + local];
    }
    if (threadIdx.x == 0) g_row2tok[row] = tok;
    const int d0 = threadIdx.x * 4;
    float4 v = make_float4(0.f, 0.f, 0.f, 0.f);
    if (tok >= 0) v = *(const float4*)(x + (size_t)tok * D_MODEL + d0);
    union { __half b[4]; uint2 u; } H;
    H.b[0] = __float2half(v.x); H.b[1] = __float2half(v.y);
    H.b[2] = __float2half(v.z); H.b[3] = __float2half(v.w);
    *(uint2*)(g_xh + (size_t)row * D_MODEL + d0) = H.u;
}

// ---------------------------------------------------------------------------
// transpose_w: [E][K][N] fp32 -> [E][N][K] fp16  (round-6 verified)
// ---------------------------------------------------------------------------
template<int WHICH>  // 1 -> W1, 2 -> W2
__global__ __launch_bounds__(256)
void transpose_w_kernel(const float* __restrict__ W, int K, int N) {
    __shared__ float t[64][65];
    const int e = blockIdx.z, k0 = blockIdx.x * 64, n0 = blockIdx.y * 64;
    const int tid = threadIdx.x;
    __half* __restrict__ Wh = (WHICH == 1) ? g_W1h : g_W2h;

    const int c4 = tid & 15, r0 = tid >> 4;
    #pragma unroll
    for (int i = 0; i < 4; i++) {
        const int kr = r0 + i * 16;
        const float4 v = *(const float4*)(W + ((size_t)e * K + k0 + kr) * N + n0 + c4 * 4);
        t[kr][c4 * 4 + 0] = v.x; t[kr][c4 * 4 + 1] = v.y;
        t[kr][c4 * 4 + 2] = v.z; t[kr][c4 * 4 + 3] = v.w;
    }
    __syncthreads();
    #pragma unroll
    for (int i = 0; i < 2; i++) {
        const int u = tid + 256 * i;
        const int n = u >> 3, ch = u & 7;
        union { __half h[8]; uint4 q; } P;
        #pragma unroll
        for (int j = 0; j < 8; j++) P.h[j] = __float2half(t[ch * 8 + j][n]);
        *(uint4*)(Wh + ((size_t)e * N + n0 + n) * K + k0 + ch * 8) = P.q;
    }
}

// ---------------------------------------------------------------------------
// fp16 mma grouped GEMM: 128x128 tile, BK=32, 3-stage cp.async ring,
// 2 CTAs/SM. Warps: 4(m) x 2(n), warp tile 32m x 64n. acc = 64 floats.
// stage: A 8K | B 8K = 16K; 3 stages = 48K   (round-9 verified, byte-identical)
// ---------------------------------------------------------------------------
#define STAGE_BYTES 16384
#define SMEM_GEMM   (3 * STAGE_BYTES)

template<int R>
__device__ __forceinline__ void stage_cp(const __half* __restrict__ src,
                                         int ld, uint32_t dst, int tid) {
    #pragma unroll
    for (int u = tid; u < R * 4; u += 256) {
        const int r = u >> 2, c = u & 3;
        const uint32_t d = dst + r * 64 + (((c ^ ((r >> 1) & 3)) & 3) << 4);
        CP_ASYNC16(d, src + (size_t)r * ld + c * 8);
    }
}

template<int KTOT, int NTOT, bool IS_G1>
__global__ __launch_bounds__(256, 2)
void moe_gemm_mma(const float* __restrict__ bias, float* __restrict__ outp) {
    const int e = g_tile_expert[blockIdx.y];
    if (e < 0) return;
    const int m0 = blockIdx.y * 128;
    const int n0 = blockIdx.x * 128;

    extern __shared__ char smem[];
    const uint32_t sb = smem_u32(smem);
    const int tid = threadIdx.x, lane = tid & 31, wid = tid >> 5;
    const int wm = (wid & 3) * 32;        // warp m-base (4 warps in m)
    const int wn = (wid >> 2) * 64;       // warp n-base (2 warps in n)

    const __half* Ah = (IS_G1 ? g_xh : g_Hh) + (size_t)m0 * KTOT;
    const __half* Bw = (IS_G1 ? g_W1h : g_W2h) + ((size_t)e * NTOT + n0) * KTOT;

    // ldmatrix lane addressing (verified)
    const int a_r = wm + (lane & 15);                       // + mt*16
    const int a_k = (lane >> 4) * 8;                        // + ks*16
    const int b_r = wn + (lane & 7) + ((lane >> 4) << 3);   // + nt*16
    const int b_k = ((lane >> 3) & 1) * 8;                  // + ks*16

    float acc[64];
    #pragma unroll
    for (int i = 0; i < 64; i++) acc[i] = 0.f;

    const int NSTAGE = KTOT / 32;

    auto issue = [&](int s, int buf) {
        const uint32_t base = sb + buf * STAGE_BYTES;
        const int k0 = s * 32;
        stage_cp<128>(Ah + k0, KTOT, base,        tid);
        stage_cp<128>(Bw + k0, KTOT, base + 8192, tid);
    };

    issue(0, 0); CP_COMMIT();
    issue(1, 1); CP_COMMIT();

    int buf = 0;
    #pragma unroll 1
    for (int s = 0; s < NSTAGE; s++) {
        CP_WAIT1();
        __syncthreads();
        const int nbuf = (buf + 2 >= 3) ? buf - 1 : buf + 2;
        if (s + 2 < NSTAGE) issue(s + 2, nbuf);
        CP_COMMIT();

        const uint32_t As = sb + buf * STAGE_BYTES;
        const uint32_t Bs = As + 8192;
        #pragma unroll
        for (int ks = 0; ks < 2; ks++) {
            uint32_t a[2][4];
            #pragma unroll
            for (int mt = 0; mt < 2; mt++)
                ldsm4(a[mt], As + sw_off(a_r + mt * 16, ks * 16 + a_k));
            #pragma unroll
            for (int nt = 0; nt < 4; nt++) {
                uint32_t b[4];
                ldsm4(b, Bs + sw_off(b_r + nt * 16, ks * 16 + b_k));
                #pragma unroll
                for (int mt = 0; mt < 2; mt++) {
                    float* d0 = acc + (mt * 8 + 2 * nt) * 4;
                    float* d1 = acc + (mt * 8 + 2 * nt + 1) * 4;
                    mma16816(d0, a[mt], b);
                    mma16816(d1, a[mt], b + 2);
                }
            }
        }
        buf = (buf + 1 == 3) ? 0 : buf + 1;
    }

    // ---- epilogue (verified mapping) ----
    const int gq = lane >> 2, tq = lane & 3;
    #pragma unroll
    for (int mt = 0; mt < 2; mt++) {
        #pragma unroll
        for (int half = 0; half < 2; half++) {   // row, row+8
            const int row = m0 + wm + mt * 16 + gq + half * 8;
            int tok = 0; float gate = 0.f;
            if (!IS_G1) {
                tok = g_row2tok[row];
                if (tok >= 0) gate = g_gate[tok];
            }
            #pragma unroll
            for (int nt = 0; nt < 8; nt++) {
                const int col = n0 + wn + nt * 8 + tq * 2;
                const float* d = acc + (mt * 8 + nt) * 4 + half * 2;
                if (IS_G1) {
                    float v0 = d[0] + bias[e * D_FF + col];
                    float v1 = d[1] + bias[e * D_FF + col + 1];
                    v0 = fmaxf(v0, 0.f); v1 = fmaxf(v1, 0.f);
                    __half2 H;
                    H.x = __float2half(v0); H.y = __float2half(v1);
                    *(__half2*)(g_Hh + (size_t)row * D_FF + col) = H;
                } else if (tok >= 0) {
                    float2 o;
                    o.x = (d[0] + bias[e * D_MODEL + col])     * gate;
                    o.y = (d[1] + bias[e * D_MODEL + col + 1]) * gate;
                    *(float2*)(outp + (size_t)tok * D_MODEL + col) = o;
                }
            }
        }
    }
}

// ---------------------------------------------------------------------------
// kernel_launch: fork-join — transposes on side stream overlap router chain
// and GEMM1. Capture-safe (event fork/join), allocation-free, deterministic.
// ---------------------------------------------------------------------------
extern "C" void kernel_launch(void* const* d_in, const int* in_sizes, int n_in,
                              void* d_out, int out_size) {
    const float* x  = (const float*)d_in[0];
    const float* rW = (const float*)d_in[1];
    const float* rb = (const float*)d_in[2];
    const float* W1 = (const float*)d_in[3];
    const float* b1 = (const float*)d_in[4];
    const float* W2 = (const float*)d_in[5];
    const float* b2 = (const float*)d_in[6];
    float* out = (float*)d_out;

    cudaFuncSetAttribute(moe_gemm_mma<D_MODEL, D_FF, true>,
                         cudaFuncAttributeMaxDynamicSharedMemorySize, SMEM_GEMM);
    cudaFuncSetAttribute(moe_gemm_mma<D_FF, D_MODEL, false>,
                         cudaFuncAttributeMaxDynamicSharedMemorySize, SMEM_GEMM);

    // fork: side stream waits on main-stream event
    cudaEventRecord(g_ev0, 0);
    cudaStreamWaitEvent(g_sB, g_ev0, 0);

    // side stream: weight transposes (HBM-bound)
    {   // W1: K=1024, N=4096 -> [E][4096][1024]
        dim3 grid(D_MODEL / 64, D_FF / 64, NEXP);
        transpose_w_kernel<1><<<grid, 256, 0, g_sB>>>(W1, D_MODEL, D_FF);
        cudaEventRecord(g_evT1, g_sB);
    }
    {   // W2: K=4096, N=1024 -> [E][1024][4096]
        dim3 grid(D_FF / 64, D_MODEL / 64, NEXP);
        transpose_w_kernel<2><<<grid, 256, 0, g_sB>>>(W2, D_FF, D_MODEL);
        cudaEventRecord(g_evT2, g_sB);
    }

    // main stream: routing chain (concurrent with T1)
    init_kernel<<<1, 32>>>();
    router_kernel<<<NTOK, 256>>>(x, rW, rb);
    build_kernel<<<1, 32>>>();
    convert_x_kernel<<<NROWPAD, 256>>>(x);

    // GEMM1 needs convert_x + T1; T2 keeps running alongside GEMM1
    cudaStreamWaitEvent(0, g_evT1, 0);
    {   // GEMM1: H = relu(Xp @ W1t^T + b1), K=1024, N=4096
        dim3 grid(D_FF / 128, MAXTILES);
        moe_gemm_mma<D_MODEL, D_FF, true><<<grid, 256, SMEM_GEMM>>>(b1, nullptr);
    }
    // GEMM2 needs GEMM1 + T2 (join side stream back into capture stream)
    cudaStreamWaitEvent(0, g_evT2, 0);
    {   // GEMM2: out = gate * (H @ W2t^T + b2), K=4096, N=1024
        dim3 grid(D_MODEL / 128, MAXTILES);
        moe_gemm_mma<D_FF, D_MODEL, false><<<grid, 256, SMEM_GEMM>>>(b2, out);
    }
}

// round 13
// speedup vs baseline: 1.1099x; 1.0768x over previous
#include <cuda_runtime.h>
#include <cuda_fp16.h>
#include <cstdint>

#define D_MODEL 1024
#define D_FF    4096
#define NEXP    8
#define NTOK    4096
#define MAXTILES 40
#define NROWPAD (MAXTILES * 128)   // 5120 padded rows

// ---------------------------------------------------------------------------
// Device-global scratch (allocation-free, graph-capture safe)
// ---------------------------------------------------------------------------
__device__ int   g_tok[NEXP * NTOK];
__device__ int   g_cnt[NEXP];
__device__ float g_gate[NTOK];
__device__ int   g_poff[NEXP];
__device__ int   g_tile_expert[MAXTILES];
__device__ int   g_row2tok[NROWPAD];

__device__ __align__(16) __half g_xh[(size_t)NROWPAD * D_MODEL];
__device__ __align__(16) __half g_W1h[(size_t)NEXP * D_FF * D_MODEL];  // [E][N][K]
__device__ __align__(16) __half g_W2h[(size_t)NEXP * D_MODEL * D_FF];  // [E][N][K]
__device__ __align__(16) __half g_Hh[(size_t)NROWPAD * D_FF];

// ---------------------------------------------------------------------------
// side stream + fork/join events (static init, reused every call)
// ---------------------------------------------------------------------------
static cudaStream_t g_sB;
static cudaEvent_t  g_ev0, g_evT1, g_evT2;
static struct StreamInit {
    StreamInit() {
        cudaStreamCreateWithFlags(&g_sB, cudaStreamNonBlocking);
        cudaEventCreateWithFlags(&g_ev0,  cudaEventDisableTiming);
        cudaEventCreateWithFlags(&g_evT1, cudaEventDisableTiming);
        cudaEventCreateWithFlags(&g_evT2, cudaEventDisableTiming);
    }
} g_stream_init;

// ---------------------------------------------------------------------------
// helpers
// ---------------------------------------------------------------------------
__device__ __forceinline__ uint32_t smem_u32(const void* p) {
    uint32_t a;
    asm("{ .reg .u64 t; cvta.to.shared.u64 t, %1; cvt.u32.u64 %0, t; }"
        : "=r"(a) : "l"(p));
    return a;
}
// swizzled byte offset into a [rows][32 halfs] (64B/row) smem tile
__device__ __forceinline__ uint32_t sw_off(int r, int kelem) {
    const int chunk = kelem >> 3;                       // 16B chunk within row
    return (uint32_t)(r * 64 + (((chunk ^ ((r >> 1) & 3)) & 3) << 4)
                      + ((kelem & 7) << 1));
}
__device__ __forceinline__ void ldsm4(uint32_t* r, uint32_t addr) {
    asm volatile("ldmatrix.sync.aligned.m8n8.x4.shared.b16 {%0,%1,%2,%3}, [%4];"
                 : "=r"(r[0]), "=r"(r[1]), "=r"(r[2]), "=r"(r[3]) : "r"(addr));
}
__device__ __forceinline__ void mma16816(float* d, const uint32_t* a,
                                         const uint32_t* b) {
    asm volatile("mma.sync.aligned.m16n8k16.row.col.f32.f16.f16.f32 "
                 "{%0,%1,%2,%3}, {%4,%5,%6,%7}, {%8,%9}, {%0,%1,%2,%3};"
                 : "+f"(d[0]), "+f"(d[1]), "+f"(d[2]), "+f"(d[3])
                 : "r"(a[0]), "r"(a[1]), "r"(a[2]), "r"(a[3]),
                   "r"(b[0]), "r"(b[1]));
}
#define CP_ASYNC16(dst, src) \
    asm volatile("cp.async.cg.shared.global [%0], [%1], 16;" :: "r"(dst), "l"(src))
#define CP_COMMIT()  asm volatile("cp.async.commit_group;" ::: "memory")
#define CP_WAIT1()   asm volatile("cp.async.wait_group 1;" ::: "memory")

// ---------------------------------------------------------------------------
// init / build  (unchanged, verified)
// ---------------------------------------------------------------------------
__global__ void init_kernel() {
    if (threadIdx.x < NEXP) g_cnt[threadIdx.x] = 0;
}

__global__ void build_kernel() {
    if (threadIdx.x != 0) return;
    int off = 0;
    for (int e = 0; e < NEXP; e++) {
        g_poff[e] = off;
        int tiles = (g_cnt[e] + 127) >> 7;
        for (int t = 0; t < tiles; t++) g_tile_expert[(off >> 7) + t] = e;
        off += tiles << 7;
    }
    for (int t = off >> 7; t < MAXTILES; t++) g_tile_expert[t] = -1;
}

// ---------------------------------------------------------------------------
// router v2: 8 tokens/block, rW^T staged in padded smem, 8 accumulators/lane.
// LDS per 8 FMA = 9 conflict-free floats (vs 1 LDS + 1 L1-global per FMA).
// ---------------------------------------------------------------------------
#define RT_SMEM ((8 * 1032 + 8 * 1024) * 4)   // 65,792 B

__global__ __launch_bounds__(256)
void router_kernel(const float* __restrict__ x,
                   const float* __restrict__ rW,
                   const float* __restrict__ rb) {
    extern __shared__ float sm[];
    float* rWT = sm;                 // [8][1032] padded: bank = (8e+d)%32
    float* xs  = sm + 8 * 1032;     // [8][1024]
    const int tid = threadIdx.x, wid = tid >> 5, lane = tid & 31;

    // stage rW transposed (coalesced global, conflict-free smem via pad)
    #pragma unroll
    for (int i = tid; i < D_MODEL * NEXP; i += 256) {
        const int d = i >> 3, e = i & 7;
        rWT[e * 1032 + d] = rW[i];
    }
    // stage this warp's token row
    const int token = blockIdx.x * 8 + wid;
    {
        const float4* xr = (const float4*)(x + (size_t)token * D_MODEL);
        float4* xd = (float4*)(xs + wid * 1024);
        #pragma unroll
        for (int i = 0; i < 8; i++) xd[lane + 32 * i] = xr[lane + 32 * i];
    }
    __syncthreads();

    float acc[8];
    #pragma unroll
    for (int e = 0; e < 8; e++) acc[e] = 0.f;
    #pragma unroll 4
    for (int k = 0; k < 32; k++) {
        const int d = lane + k * 32;
        const float xv = xs[wid * 1024 + d];
        #pragma unroll
        for (int e = 0; e < 8; e++)
            acc[e] = fmaf(xv, rWT[e * 1032 + d], acc[e]);
    }
    #pragma unroll
    for (int e = 0; e < 8; e++)
        #pragma unroll
        for (int o = 16; o > 0; o >>= 1)
            acc[e] += __shfl_xor_sync(0xffffffffu, acc[e], o);

    if (lane == 0) {
        float lg[8];
        lg[0] = acc[0] + rb[0];
        float mx = lg[0]; int am = 0;
        #pragma unroll
        for (int e = 1; e < 8; e++) {
            lg[e] = acc[e] + rb[e];
            if (lg[e] > mx) { mx = lg[e]; am = e; }   // first-max, matches argmax
        }
        float sum = 0.f;
        #pragma unroll
        for (int e = 0; e < 8; e++) sum += expf(lg[e] - mx);
        const int pos = atomicAdd(&g_cnt[am], 1);
        g_tok[am * NTOK + pos] = token;
        g_gate[token] = 1.0f / sum;
    }
}

// ---------------------------------------------------------------------------
// convert_x: gather token rows into packed/padded order, fp16
// ---------------------------------------------------------------------------
__global__ void convert_x_kernel(const float* __restrict__ x) {
    const int row = blockIdx.x;
    const int e = g_tile_expert[row >> 7];
    int tok = -1;
    if (e >= 0) {
        const int local = row - g_poff[e];
        if (local < g_cnt[e]) tok = g_tok[e * NTOK + local];
    }
    if (threadIdx.x == 0) g_row2tok[row] = tok;
    const int d0 = threadIdx.x * 4;
    float4 v = make_float4(0.f, 0.f, 0.f, 0.f);
    if (tok >= 0) v = *(const float4*)(x + (size_t)tok * D_MODEL + d0);
    union { __half b[4]; uint2 u; } H;
    H.b[0] = __float2half(v.x); H.b[1] = __float2half(v.y);
    H.b[2] = __float2half(v.z); H.b[3] = __float2half(v.w);
    *(uint2*)(g_xh + (size_t)row * D_MODEL + d0) = H.u;
}

// ---------------------------------------------------------------------------
// transpose_w: [E][K][N] fp32 -> [E][N][K] fp16  (round-6 verified)
// ---------------------------------------------------------------------------
template<int WHICH>  // 1 -> W1, 2 -> W2
__global__ __launch_bounds__(256)
void transpose_w_kernel(const float* __restrict__ W, int K, int N) {
    __shared__ float t[64][65];
    const int e = blockIdx.z, k0 = blockIdx.x * 64, n0 = blockIdx.y * 64;
    const int tid = threadIdx.x;
    __half* __restrict__ Wh = (WHICH == 1) ? g_W1h : g_W2h;

    const int c4 = tid & 15, r0 = tid >> 4;
    #pragma unroll
    for (int i = 0; i < 4; i++) {
        const int kr = r0 + i * 16;
        const float4 v = *(const float4*)(W + ((size_t)e * K + k0 + kr) * N + n0 + c4 * 4);
        t[kr][c4 * 4 + 0] = v.x; t[kr][c4 * 4 + 1] = v.y;
        t[kr][c4 * 4 + 2] = v.z; t[kr][c4 * 4 + 3] = v.w;
    }
    __syncthreads();
    #pragma unroll
    for (int i = 0; i < 2; i++) {
        const int u = tid + 256 * i;
        const int n = u >> 3, ch = u & 7;
        union { __half h[8]; uint4 q; } P;
        #pragma unroll
        for (int j = 0; j < 8; j++) P.h[j] = __float2half(t[ch * 8 + j][n]);
        *(uint4*)(Wh + ((size_t)e * N + n0 + n) * K + k0 + ch * 8) = P.q;
    }
}

// ---------------------------------------------------------------------------
// fp16 mma grouped GEMM: 128x128 tile, BK=32, 3-stage cp.async ring,
// 2 CTAs/SM. Warps: 4(m) x 2(n), warp tile 32m x 64n. acc = 64 floats.
// stage: A 8K | B 8K = 16K; 3 stages = 48K   (round-9 verified, byte-identical)
// ---------------------------------------------------------------------------
#define STAGE_BYTES 16384
#define SMEM_GEMM   (3 * STAGE_BYTES)

template<int R>
__device__ __forceinline__ void stage_cp(const __half* __restrict__ src,
                                         int ld, uint32_t dst, int tid) {
    #pragma unroll
    for (int u = tid; u < R * 4; u += 256) {
        const int r = u >> 2, c = u & 3;
        const uint32_t d = dst + r * 64 + (((c ^ ((r >> 1) & 3)) & 3) << 4);
        CP_ASYNC16(d, src + (size_t)r * ld + c * 8);
    }
}

template<int KTOT, int NTOT, bool IS_G1>
__global__ __launch_bounds__(256, 2)
void moe_gemm_mma(const float* __restrict__ bias, float* __restrict__ outp) {
    const int e = g_tile_expert[blockIdx.y];
    if (e < 0) return;
    const int m0 = blockIdx.y * 128;
    const int n0 = blockIdx.x * 128;

    extern __shared__ char smem[];
    const uint32_t sb = smem_u32(smem);
    const int tid = threadIdx.x, lane = tid & 31, wid = tid >> 5;
    const int wm = (wid & 3) * 32;        // warp m-base (4 warps in m)
    const int wn = (wid >> 2) * 64;       // warp n-base (2 warps in n)

    const __half* Ah = (IS_G1 ? g_xh : g_Hh) + (size_t)m0 * KTOT;
    const __half* Bw = (IS_G1 ? g_W1h : g_W2h) + ((size_t)e * NTOT + n0) * KTOT;

    // ldmatrix lane addressing (verified)
    const int a_r = wm + (lane & 15);                       // + mt*16
    const int a_k = (lane >> 4) * 8;                        // + ks*16
    const int b_r = wn + (lane & 7) + ((lane >> 4) << 3);   // + nt*16
    const int b_k = ((lane >> 3) & 1) * 8;                  // + ks*16

    float acc[64];
    #pragma unroll
    for (int i = 0; i < 64; i++) acc[i] = 0.f;

    const int NSTAGE = KTOT / 32;

    auto issue = [&](int s, int buf) {
        const uint32_t base = sb + buf * STAGE_BYTES;
        const int k0 = s * 32;
        stage_cp<128>(Ah + k0, KTOT, base,        tid);
        stage_cp<128>(Bw + k0, KTOT, base + 8192, tid);
    };

    issue(0, 0); CP_COMMIT();
    issue(1, 1); CP_COMMIT();

    int buf = 0;
    #pragma unroll 1
    for (int s = 0; s < NSTAGE; s++) {
        CP_WAIT1();
        __syncthreads();
        const int nbuf = (buf + 2 >= 3) ? buf - 1 : buf + 2;
        if (s + 2 < NSTAGE) issue(s + 2, nbuf);
        CP_COMMIT();

        const uint32_t As = sb + buf * STAGE_BYTES;
        const uint32_t Bs = As + 8192;
        #pragma unroll
        for (int ks = 0; ks < 2; ks++) {
            uint32_t a[2][4];
            #pragma unroll
            for (int mt = 0; mt < 2; mt++)
                ldsm4(a[mt], As + sw_off(a_r + mt * 16, ks * 16 + a_k));
            #pragma unroll
            for (int nt = 0; nt < 4; nt++) {
                uint32_t b[4];
                ldsm4(b, Bs + sw_off(b_r + nt * 16, ks * 16 + b_k));
                #pragma unroll
                for (int mt = 0; mt < 2; mt++) {
                    float* d0 = acc + (mt * 8 + 2 * nt) * 4;
                    float* d1 = acc + (mt * 8 + 2 * nt + 1) * 4;
                    mma16816(d0, a[mt], b);
                    mma16816(d1, a[mt], b + 2);
                }
            }
        }
        buf = (buf + 1 == 3) ? 0 : buf + 1;
    }

    // ---- epilogue (verified mapping) ----
    const int gq = lane >> 2, tq = lane & 3;
    #pragma unroll
    for (int mt = 0; mt < 2; mt++) {
        #pragma unroll
        for (int half = 0; half < 2; half++) {   // row, row+8
            const int row = m0 + wm + mt * 16 + gq + half * 8;
            int tok = 0; float gate = 0.f;
            if (!IS_G1) {
                tok = g_row2tok[row];
                if (tok >= 0) gate = g_gate[tok];
            }
            #pragma unroll
            for (int nt = 0; nt < 8; nt++) {
                const int col = n0 + wn + nt * 8 + tq * 2;
                const float* d = acc + (mt * 8 + nt) * 4 + half * 2;
                if (IS_G1) {
                    float v0 = d[0] + bias[e * D_FF + col];
                    float v1 = d[1] + bias[e * D_FF + col + 1];
                    v0 = fmaxf(v0, 0.f); v1 = fmaxf(v1, 0.f);
                    __half2 H;
                    H.x = __float2half(v0); H.y = __float2half(v1);
                    *(__half2*)(g_Hh + (size_t)row * D_FF + col) = H;
                } else if (tok >= 0) {
                    float2 o;
                    o.x = (d[0] + bias[e * D_MODEL + col])     * gate;
                    o.y = (d[1] + bias[e * D_MODEL + col + 1]) * gate;
                    *(float2*)(outp + (size_t)tok * D_MODEL + col) = o;
                }
            }
        }
    }
}

// ---------------------------------------------------------------------------
// kernel_launch: fork-join overlap (round-12 verified) + router v2
// ---------------------------------------------------------------------------
extern "C" void kernel_launch(void* const* d_in, const int* in_sizes, int n_in,
                              void* d_out, int out_size) {
    const float* x  = (const float*)d_in[0];
    const float* rW = (const float*)d_in[1];
    const float* rb = (const float*)d_in[2];
    const float* W1 = (const float*)d_in[3];
    const float* b1 = (const float*)d_in[4];
    const float* W2 = (const float*)d_in[5];
    const float* b2 = (const float*)d_in[6];
    float* out = (float*)d_out;

    cudaFuncSetAttribute(moe_gemm_mma<D_MODEL, D_FF, true>,
                         cudaFuncAttributeMaxDynamicSharedMemorySize, SMEM_GEMM);
    cudaFuncSetAttribute(moe_gemm_mma<D_FF, D_MODEL, false>,
                         cudaFuncAttributeMaxDynamicSharedMemorySize, SMEM_GEMM);
    cudaFuncSetAttribute(router_kernel,
                         cudaFuncAttributeMaxDynamicSharedMemorySize, RT_SMEM);

    // fork: side stream waits on main-stream event
    cudaEventRecord(g_ev0, 0);
    cudaStreamWaitEvent(g_sB, g_ev0, 0);

    // side stream: weight transposes (HBM-bound)
    {   // W1: K=1024, N=4096 -> [E][4096][1024]
        dim3 grid(D_MODEL / 64, D_FF / 64, NEXP);
        transpose_w_kernel<1><<<grid, 256, 0, g_sB>>>(W1, D_MODEL, D_FF);
        cudaEventRecord(g_evT1, g_sB);
    }
    {   // W2: K=4096, N=1024 -> [E][1024][4096]
        dim3 grid(D_FF / 64, D_MODEL / 64, NEXP);
        transpose_w_kernel<2><<<grid, 256, 0, g_sB>>>(W2, D_FF, D_MODEL);
        cudaEventRecord(g_evT2, g_sB);
    }

    // main stream: routing chain (concurrent with T1)
    init_kernel<<<1, 32>>>();
    router_kernel<<<NTOK / 8, 256, RT_SMEM>>>(x, rW, rb);
    build_kernel<<<1, 32>>>();
    convert_x_kernel<<<NROWPAD, 256>>>(x);

    // GEMM1 needs convert_x + T1; T2 keeps running alongside GEMM1
    cudaStreamWaitEvent(0, g_evT1, 0);
    {   // GEMM1: H = relu(Xp @ W1t^T + b1), K=1024, N=4096
        dim3 grid(D_FF / 128, MAXTILES);
        moe_gemm_mma<D_MODEL, D_FF, true><<<grid, 256, SMEM_GEMM>>>(b1, nullptr);
    }
    // GEMM2 needs GEMM1 + T2 (join side stream back into capture stream)
    cudaStreamWaitEvent(0, g_evT2, 0);
    {   // GEMM2: out = gate * (H @ W2t^T + b2), K=4096, N=1024
        dim3 grid(D_MODEL / 128, MAXTILES);
        moe_gemm_mma<D_FF, D_MODEL, false><<<grid, 256, SMEM_GEMM>>>(b2, out);
    }
}